// round 16
// baseline (speedup 1.0000x reference)
#include <cuda_runtime.h>
#include <cuda_fp16.h>
#include <mma.h>

using namespace nvcuda;

#define NUM_NODE 50000
#define NUM_EDGE 25000
#define NNZ      800000
#define D        128
#define NSEG     (NUM_EDGE + NUM_NODE)               // 75000 segments

#define ECAP 96                                      // slots per edge bucket
#define VCAP 64                                      // slots per node bucket

#define GEMM_TILES  ((NUM_NODE + 31) / 32)           // 1563 tiles of 32 rows
#define HIST_BLOCKS ((NNZ / 4 + 255) / 256)          // 782 (4 incidences/thread)
#define EDGE_BLOCKS (NUM_EDGE / 8)                   // 3125 (8 warps/block)
#define NODE_BLOCKS (NUM_NODE / 8)                   // 6250

#define WPAD 136                                     // padded half row (ws)
#define RPAD 72                                      // padded half row (rs)

// ---------------- scratch (static device globals; zero-initialized) -------
__device__ __half g_Xh [NUM_NODE * D];   // input @ weight, fp16 (12.8 MB)
__device__ __half g_Xeh[NUM_EDGE * D];   // edge features, fp16 (6.4 MB)
__device__ int g_cnt[NSEG];              // counts; self-zeroed by the means
__device__ int g_ple[NUM_EDGE * ECAP];   // padded edge buckets: node ids (9.6 MB)
__device__ int g_plv[NUM_NODE * VCAP];   // padded node buckets: edge ids (12.8 MB)

// ---------------- L1a: hist + direct padded scatter (standalone, lean) -----
// 4 incidences per thread via int4: 8 INDEPENDENT atomics in flight, then
// 8 stores. ~24 regs -> full occupancy (the fused version was throttled to
// 17.7% occ by the GEMM role's 142 regs).
__global__ __launch_bounds__(256) void hist_kernel(const int* __restrict__ V,
                                                   const int* __restrict__ E) {
    int i4 = blockIdx.x * blockDim.x + threadIdx.x;   // 0..NNZ/4-1
    if (i4 < NNZ / 4) {
        int4 e = ((const int4*)E)[i4];
        int4 v = ((const int4*)V)[i4];
        int re0 = atomicAdd(&g_cnt[e.x], 1);
        int re1 = atomicAdd(&g_cnt[e.y], 1);
        int re2 = atomicAdd(&g_cnt[e.z], 1);
        int re3 = atomicAdd(&g_cnt[e.w], 1);
        int rv0 = atomicAdd(&g_cnt[NUM_EDGE + v.x], 1);
        int rv1 = atomicAdd(&g_cnt[NUM_EDGE + v.y], 1);
        int rv2 = atomicAdd(&g_cnt[NUM_EDGE + v.z], 1);
        int rv3 = atomicAdd(&g_cnt[NUM_EDGE + v.w], 1);
        if (re0 < ECAP) g_ple[e.x * ECAP + re0] = v.x;   // P(overflow) < 1e-13
        if (re1 < ECAP) g_ple[e.y * ECAP + re1] = v.y;
        if (re2 < ECAP) g_ple[e.z * ECAP + re2] = v.z;
        if (re3 < ECAP) g_ple[e.w * ECAP + re3] = v.w;
        if (rv0 < VCAP) g_plv[v.x * VCAP + rv0] = e.x;
        if (rv1 < VCAP) g_plv[v.y * VCAP + rv1] = e.y;
        if (rv2 < VCAP) g_plv[v.z * VCAP + rv2] = e.z;
        if (rv3 < VCAP) g_plv[v.w * VCAP + rv3] = e.w;
    }
}

// ---------------- L1b: GEMM standalone (proven fp16 wmma role) -------------
__global__ __launch_bounds__(128) void gemm_kernel(const float* __restrict__ in,
                                                   const float* __restrict__ w) {
    __shared__ __align__(16) __half ws[64 * WPAD];   // 17.4 KB weight K-tile
    __shared__ __align__(16) __half rs[32 * RPAD];   // 4.6 KB input K-tile
    __shared__ __align__(16) float  cs[4][16 * 16];  // 4 KB per-warp C staging
    int t    = threadIdx.x;
    int warp = t >> 5;
    int lane = t & 31;
    int tile = blockIdx.x;
    int row0  = tile * 32;
    int mrow  = (warp & 1) * 16;
    int ncol0 = (warp >> 1) * 64;

    wmma::fragment<wmma::accumulator, 16, 16, 16, float> acc[4];
    #pragma unroll
    for (int i = 0; i < 4; i++) wmma::fill_fragment(acc[i], 0.0f);

    #pragma unroll
    for (int kt = 0; kt < 2; kt++) {
        __syncthreads();
        {
            const float4* src = (const float4*)(w + (size_t)kt * 64 * D);
            #pragma unroll
            for (int i = 0; i < 16; i++) {
                int idx = t + 128 * i;
                int r = idx >> 5, c4 = idx & 31;
                float4 v = src[r * 32 + c4];
                half2 h0 = __floats2half2_rn(v.x, v.y);
                half2 h1 = __floats2half2_rn(v.z, v.w);
                *(half2*)&ws[r * WPAD + c4 * 4]     = h0;
                *(half2*)&ws[r * WPAD + c4 * 4 + 2] = h1;
            }
        }
        {
            #pragma unroll
            for (int i = 0; i < 4; i++) {
                int idx = t + 128 * i;
                int r = idx >> 4, c4 = idx & 15;
                int grow = row0 + r;
                float4 v = make_float4(0.f, 0.f, 0.f, 0.f);
                if (grow < NUM_NODE)
                    v = ((const float4*)(in + (size_t)grow * D + kt * 64))[c4];
                half2 h0 = __floats2half2_rn(v.x, v.y);
                half2 h1 = __floats2half2_rn(v.z, v.w);
                *(half2*)&rs[r * RPAD + c4 * 4]     = h0;
                *(half2*)&rs[r * RPAD + c4 * 4 + 2] = h1;
            }
        }
        __syncthreads();

        #pragma unroll
        for (int ks = 0; ks < 4; ks++) {
            wmma::fragment<wmma::matrix_a, 16, 16, 16, __half, wmma::row_major> af;
            wmma::load_matrix_sync(af, &rs[mrow * RPAD + ks * 16], RPAD);
            #pragma unroll
            for (int nf = 0; nf < 4; nf++) {
                wmma::fragment<wmma::matrix_b, 16, 16, 16, __half, wmma::row_major> bf;
                wmma::load_matrix_sync(bf, &ws[ks * 16 * WPAD + ncol0 + nf * 16], WPAD);
                wmma::mma_sync(acc[nf], af, bf, acc[nf]);
            }
        }
    }

    #pragma unroll
    for (int nf = 0; nf < 4; nf++) {
        wmma::store_matrix_sync(&cs[warp][0], acc[nf], 16, wmma::mem_row_major);
        __syncwarp();
        #pragma unroll
        for (int j = 0; j < 4; j++) {
            int h = lane + 32 * j;
            int r = h >> 3, c2 = h & 7;
            int grow = row0 + mrow + r;
            if (grow < NUM_NODE) {
                float2 f = ((const float2*)&cs[warp][0])[h];
                ((half2*)(g_Xh + (size_t)grow * D))[(ncol0 + nf * 16) / 2 + c2] =
                    __floats2half2_rn(f.x, f.y);
            }
        }
        __syncwarp();
    }
}

// ---------------- fp16 gather helper (proven) ------------------------------
__device__ __forceinline__ void acc_h4(float4& a, float2 raw) {
    __half2 h01 = *reinterpret_cast<__half2*>(&raw.x);
    __half2 h23 = *reinterpret_cast<__half2*>(&raw.y);
    float2 f01 = __half22float2(h01);
    float2 f23 = __half22float2(h23);
    a.x += f01.x; a.y += f01.y; a.z += f23.x; a.w += f23.y;
}

// ---------------- L2: edge mean over padded buckets (self-zeroing) ---------
__global__ __launch_bounds__(256) void edge_mean_kernel() {
    int gw   = blockIdx.x * 8 + (threadIdx.x >> 5);
    int lane = threadIdx.x & 31;
    int cnt  = g_cnt[gw];
    if (cnt > ECAP) cnt = ECAP;
    const int* bucket = g_ple + (size_t)gw * ECAP;

    float4 acc = make_float4(0.f, 0.f, 0.f, 0.f);
    int j = 0;
    for (; j + 4 <= cnt; j += 4) {
        int n0 = bucket[j], n1 = bucket[j + 1];
        int n2 = bucket[j + 2], n3 = bucket[j + 3];
        float2 a0 = ((const float2*)(g_Xh + (size_t)n0 * D))[lane];
        float2 a1 = ((const float2*)(g_Xh + (size_t)n1 * D))[lane];
        float2 a2 = ((const float2*)(g_Xh + (size_t)n2 * D))[lane];
        float2 a3 = ((const float2*)(g_Xh + (size_t)n3 * D))[lane];
        acc_h4(acc, a0); acc_h4(acc, a1); acc_h4(acc, a2); acc_h4(acc, a3);
    }
    for (; j < cnt; j++) {
        float2 a0 = ((const float2*)(g_Xh + (size_t)bucket[j] * D))[lane];
        acc_h4(acc, a0);
    }
    float s = (cnt > 0) ? (1.0f / (float)cnt) : 0.f;
    __half2 o01 = __floats2half2_rn(acc.x * s, acc.y * s);
    __half2 o23 = __floats2half2_rn(acc.z * s, acc.w * s);
    float2 st;
    *reinterpret_cast<__half2*>(&st.x) = o01;
    *reinterpret_cast<__half2*>(&st.y) = o23;
    ((float2*)(g_Xeh + (size_t)gw * D))[lane] = st;

    if (lane == 0) g_cnt[gw] = 0;          // ready for next graph replay
}

// ---------------- L3: node mean + bias, fp32 out (self-zeroing) ------------
__global__ __launch_bounds__(256) void node_mean_kernel(const float* __restrict__ bias,
                                                        float* __restrict__ out) {
    int gw   = blockIdx.x * 8 + (threadIdx.x >> 5);
    int lane = threadIdx.x & 31;
    int cnt  = g_cnt[NUM_EDGE + gw];
    if (cnt > VCAP) cnt = VCAP;
    const int* bucket = g_plv + (size_t)gw * VCAP;

    float4 acc = make_float4(0.f, 0.f, 0.f, 0.f);
    int j = 0;
    for (; j + 4 <= cnt; j += 4) {
        int e0 = bucket[j], e1 = bucket[j + 1];
        int e2 = bucket[j + 2], e3 = bucket[j + 3];
        float2 a0 = ((const float2*)(g_Xeh + (size_t)e0 * D))[lane];
        float2 a1 = ((const float2*)(g_Xeh + (size_t)e1 * D))[lane];
        float2 a2 = ((const float2*)(g_Xeh + (size_t)e2 * D))[lane];
        float2 a3 = ((const float2*)(g_Xeh + (size_t)e3 * D))[lane];
        acc_h4(acc, a0); acc_h4(acc, a1); acc_h4(acc, a2); acc_h4(acc, a3);
    }
    for (; j < cnt; j++) {
        float2 a0 = ((const float2*)(g_Xeh + (size_t)bucket[j] * D))[lane];
        acc_h4(acc, a0);
    }
    float s = (cnt > 0) ? (1.0f / (float)cnt) : 0.f;
    float4 b = *((const float4*)bias + lane);
    float4 r = make_float4(acc.x * s + b.x, acc.y * s + b.y,
                           acc.z * s + b.z, acc.w * s + b.w);
    *((float4*)&out[(size_t)gw * D] + lane) = r;

    if (lane == 0) g_cnt[NUM_EDGE + gw] = 0;   // ready for next graph replay
}

// ---------------- launch ---------------------------------------------------
extern "C" void kernel_launch(void* const* d_in, const int* in_sizes, int n_in,
                              void* d_out, int out_size) {
    const float* input  = (const float*)d_in[0];   // [50000,128]
    const float* weight = (const float*)d_in[1];   // [128,128]
    const float* bias   = (const float*)d_in[2];   // [128]
    const int*   V      = (const int*)d_in[3];     // [800000]
    const int*   E      = (const int*)d_in[4];     // [800000]
    float*       out    = (float*)d_out;           // [50000,128]

    (void)in_sizes; (void)n_in; (void)out_size;

    hist_kernel     <<<HIST_BLOCKS, 256>>>(V, E);
    gemm_kernel     <<<GEMM_TILES, 128>>>(input, weight);
    edge_mean_kernel<<<EDGE_BLOCKS, 256>>>();
    node_mean_kernel<<<NODE_BLOCKS, 256>>>(bias, out);
}